// round 14
// baseline (speedup 1.0000x reference)
#include <cuda_runtime.h>
#include <cuda_bf16.h>

#define HIMG 240
#define WIMG 135
#define HW   (HIMG * WIMG)
#define NF   1000
#define NV   600
#define INV_SIGMA 1.0e4f
#define BLURF 9.210240366975849e-4f
#define BAND  0.05f
#define SATURATE (-1.0e30f)        // log-space "covered" marker; exp -> 0

#define NT     128                 // raster block: 4 warps
#define SPLIT  8                   // row-slices per face
#define NRAST  (NF * SPLIT)        // 8000 raster blocks

// Per-face data: 6 x 16B = 96B
// q0: ax ay bx by | q1: cx cy e0x e0y | q2: e1x e1y e2x e2y
// q3: rl0 rl1 rl2 rd0 | q4: rd1 rd2 -- -- | r: x0 x1 y0 y1 (x0>x1 => skip)
struct __align__(16) FD6 {
    float4 q0, q1, q2, q3, q4;
    int4   r;
};

__device__ FD6  g_face[NF];
__device__ float g_sum[HW];        // zero at load; finalize self-cleans

// ---------------------------------------------------------------------------
// Stage 1: per-face setup (once per face, fully parallel)
// ---------------------------------------------------------------------------
__global__ void __launch_bounds__(256)
prep_kernel(const float* __restrict__ verts,
            const int*   __restrict__ faces,
            float* __restrict__ out) {
    int f = blockIdx.x * 256 + threadIdx.x;
    if (f == 0) out[0] = 0.0f;
    if (f >= NF) return;

    int idx[3];
    idx[0] = faces[3 * f + 0];
    idx[1] = faces[3 * f + 1];
    idx[2] = faces[3 * f + 2];

    float Px[3], Py[3], zs[3];
#pragma unroll
    for (int k = 0; k < 3; k++) {
        float x = verts[3 * idx[k] + 0];
        float y = verts[3 * idx[k] + 1];
        float z = verts[3 * idx[k] + 2];
        float vx = -x, vy = -y, vz = z;          // R = diag(-1,-1,1)
        zs[k] = vz;
        float zz = fmaxf(vz, 1e-6f);
        Px[k] = (__fdividef(1000.0f * vx, zz) + 512.0f) * ((float)WIMG / 1024.0f);
        Py[k] = (__fdividef(1000.0f * vy, zz) + 512.0f) * ((float)HIMG / 1024.0f);
    }
    float tz = (zs[0] + zs[1] + zs[2]) * (1.0f / 3.0f);

    float ax = Px[0], ay = Py[0];
    float bx = Px[1], by = Py[1];
    float cx = Px[2], cy = Py[2];
    float e0x = bx - ax, e0y = by - ay;
    float e1x = cx - bx, e1y = cy - by;
    float e2x = ax - cx, e2y = ay - cy;
    float l0 = e0x * e0x + e0y * e0y + 1e-12f;
    float l1 = e1x * e1x + e1y * e1y + 1e-12f;
    float l2 = e2x * e2x + e2y * e2y + 1e-12f;
    float rl0 = rsqrtf(l0), rl1 = rsqrtf(l1), rl2 = rsqrtf(l2);

    FD6 fd;
    fd.q0 = make_float4(ax, ay, bx, by);
    fd.q1 = make_float4(cx, cy, e0x, e0y);
    fd.q2 = make_float4(e1x, e1y, e2x, e2y);
    fd.q3 = make_float4(rl0, rl1, rl2, rl0 * rl0);
    fd.q4 = make_float4(rl1 * rl1, rl2 * rl2, 0.0f, 0.0f);

    if (!(tz > 1e-6f)) {
        fd.r = make_int4(1, 0, 1, 0);            // skip
    } else {
        float minx = fminf(ax, fminf(bx, cx));
        float maxx = fmaxf(ax, fmaxf(bx, cx));
        float miny = fminf(ay, fminf(by, cy));
        float maxy = fmaxf(ay, fmaxf(by, cy));
        int x0 = max(0, (int)floorf(minx) - 1);
        int x1 = min(WIMG - 1, (int)ceilf(maxx));
        int y0 = max(0, (int)floorf(miny) - 1);
        int y1 = min(HIMG - 1, (int)ceilf(maxy));
        // point-degenerate face: reference marks every pixel inside
        if (e0x == 0.0f && e0y == 0.0f && e1x == 0.0f && e1y == 0.0f) {
            x0 = 0; x1 = WIMG - 1; y0 = 0; y1 = HIMG - 1;
        }
        fd.r = make_int4(x0, x1, y0, y1);
    }
    g_face[f] = fd;
}

// ---------------------------------------------------------------------------
// Stage 2 (PDL): raster. Block = (face, row-slice). No smem, no syncthreads.
// ---------------------------------------------------------------------------
__global__ void __launch_bounds__(NT)
raster_kernel() {
    cudaGridDependencySynchronize();             // g_face ready

    const int tid  = threadIdx.x;
    const int lane = tid & 31;
    const int warp = tid >> 5;                   // 0..3
    const int f    = blockIdx.x >> 3;            // SPLIT == 8
    const int sl   = blockIdx.x & 7;

    const FD6 fd = g_face[f];                    // 6 uniform LDG.128 (bcast)
    const int x0 = fd.r.x, x1 = fd.r.y, y0 = fd.r.z, y1 = fd.r.w;
    if (x0 > x1) return;                         // culled face

    const float ax = fd.q0.x, ay = fd.q0.y, bx = fd.q0.z, by = fd.q0.w;
    const float cx = fd.q1.x, cy = fd.q1.y, e0x = fd.q1.z, e0y = fd.q1.w;
    const float e1x = fd.q2.x, e1y = fd.q2.y, e2x = fd.q2.z, e2y = fd.q2.w;
    const float rl0 = fd.q3.x, rl1 = fd.q3.y, rl2 = fd.q3.z, rd0 = fd.q3.w;
    const float rd1 = fd.q4.x, rd2 = fd.q4.y;

    const int nrows = y1 - y0 + 1;
    for (int r = sl + warp * SPLIT; r < nrows; r += 4 * SPLIT) {
        int   iy  = y0 + r;
        float py  = (float)iy + 0.5f;
        int   row = iy * WIMG;
        for (int ix = x0 + lane; ix <= x1; ix += 32) {
            float px = (float)ix + 0.5f;

            float apx0 = px - ax, apy0 = py - ay;
            float apx1 = px - bx, apy1 = py - by;
            float apx2 = px - cx, apy2 = py - cy;

            float c0 = e0x * apy0 - e0y * apx0;
            float c1 = e1x * apy1 - e1y * apx1;
            float c2 = e2x * apy2 - e2y * apx2;
            bool inside = (c0 >= 0.0f && c1 >= 0.0f && c2 >= 0.0f) ||
                          (c0 <= 0.0f && c1 <= 0.0f && c2 <= 0.0f);

            // conservative perpendicular line distance (<= segment distance)
            float dl = fminf(fabsf(c0) * rl0,
                       fminf(fabsf(c1) * rl1, fabsf(c2) * rl2));

            if (inside && dl > BAND) {
                // log contribution <= -25: alpha saturates to 1. All other
                // contributions are negative, so ANY interleaving with the
                // band atomics below leaves s <= -25 -> expf(s) == 0.
                __stcg(&g_sum[row + ix], SATURATE);
            } else if (inside || dl <= BAND) {
                // exact reference math (segment distances)
                float t0 = fminf(fmaxf((apx0 * e0x + apy0 * e0y) * rd0, 0.0f), 1.0f);
                float rx = apx0 - t0 * e0x;
                float ry = apy0 - t0 * e0y;
                float d2min = rx * rx + ry * ry;

                float t1 = fminf(fmaxf((apx1 * e1x + apy1 * e1y) * rd1, 0.0f), 1.0f);
                rx = apx1 - t1 * e1x;
                ry = apy1 - t1 * e1y;
                d2min = fminf(d2min, rx * rx + ry * ry);

                float t2 = fminf(fmaxf((apx2 * e2x + apy2 * e2y) * rd2, 0.0f), 1.0f);
                rx = apx2 - t2 * e2x;
                ry = apy2 - t2 * e2y;
                d2min = fminf(d2min, rx * rx + ry * ry);

                if (inside || d2min <= BLURF) {
                    float u = (inside ? d2min : -d2min) * INV_SIGMA;
                    // log1p(-sigmoid(u)) == -softplus(u)
                    float sp = (u > 15.0f) ? u : log1pf(__expf(u));
                    if (sp != 0.0f) atomicAdd(&g_sum[row + ix], -sp);
                }
            }
            // outside & dl > BAND: d2min >= dl^2 > BLURF -> reference-invalid
        }
    }
}

// ---------------------------------------------------------------------------
// Stage 3 (PDL): finalize. alpha = 1 - exp(s); self-cleans g_sum.
// ---------------------------------------------------------------------------
__global__ void __launch_bounds__(256)
finalize_kernel(const float* __restrict__ gt,
                float* __restrict__ out) {
    cudaGridDependencySynchronize();             // raster writes visible

    int i = blockIdx.x * blockDim.x + threadIdx.x;
    float local = 0.0f;
    if (i < HW) {
        float s = g_sum[i];
        g_sum[i] = 0.0f;                         // self-clean for replay
        float alpha = 1.0f - expf(s);            // s=SATURATE -> alpha=1
        out[1 + i] = alpha;
        local = fabsf(alpha - gt[i]);
    }
#pragma unroll
    for (int o = 16; o > 0; o >>= 1)
        local += __shfl_down_sync(0xffffffffu, local, o);

    __shared__ float ws[8];
    int lane = threadIdx.x & 31;
    int wid  = threadIdx.x >> 5;
    if (lane == 0) ws[wid] = local;
    __syncthreads();
    if (wid == 0) {
        local = (lane < 8) ? ws[lane] : 0.0f;
#pragma unroll
        for (int o = 4; o > 0; o >>= 1)
            local += __shfl_down_sync(0xffu, local, o);
        if (lane == 0)
            atomicAdd(out, local * (1.0f / (float)HW));
    }
}

// ---------------------------------------------------------------------------
extern "C" void kernel_launch(void* const* d_in, const int* in_sizes, int n_in,
                              void* d_out, int out_size) {
    const float* verts = nullptr;
    const float* gt    = nullptr;
    const int*   faces = nullptr;
    for (int i = 0; i < n_in; i++) {
        if (in_sizes[i] == NV * 3)      verts = (const float*)d_in[i];
        else if (in_sizes[i] == HW)     gt    = (const float*)d_in[i];
        else if (in_sizes[i] == NF * 3) faces = (const int*)d_in[i];
    }
    float* out = (float*)d_out;
    (void)out_size;

    prep_kernel<<<(NF + 255) / 256, 256>>>(verts, faces, out);

    cudaLaunchAttribute attrs[1];
    attrs[0].id = cudaLaunchAttributeProgrammaticStreamSerialization;
    attrs[0].val.programmaticStreamSerializationAllowed = 1;

    cudaLaunchConfig_t cfg = {};
    cfg.blockDim = dim3(NT, 1, 1);
    cfg.gridDim  = dim3(NRAST, 1, 1);
    cfg.stream   = 0;
    cfg.attrs    = attrs;
    cfg.numAttrs = 1;
    cudaLaunchKernelEx(&cfg, raster_kernel);

    cudaLaunchConfig_t cfg2 = {};
    cfg2.blockDim = dim3(256, 1, 1);
    cfg2.gridDim  = dim3((HW + 255) / 256, 1, 1);
    cfg2.stream   = 0;
    cfg2.attrs    = attrs;
    cfg2.numAttrs = 1;
    cudaLaunchKernelEx(&cfg2, finalize_kernel, gt, out);
}